// round 2
// baseline (speedup 1.0000x reference)
#include <cuda_runtime.h>
#include <cuda_bf16.h>
#include <math.h>

// Problem constants (fixed by setup_inputs)
#define V_N   20000
#define D_K   256
#define NHEAD 4
#define O_DIM 128
#define NCOL  512   // NHEAD * O_DIM
#define KNBR  16

// ---------------- scratch (no allocations allowed) ----------------
__device__ float g_t[(size_t)V_N * NCOL];     // t concat over heads: [V, H*O], 41 MB
__device__ float g_attn[NHEAD * V_N];          // attn[h*V + v]
__device__ float g_wa[NHEAD * D_K];            // wa[h*D + d]
__device__ float g_Bh[D_K * NCOL];             // W repacked [d][h*O+o], tf32 hi
__device__ float g_Bl[D_K * NCOL];             // tf32 lo residual
__device__ int   g_adj64;                      // 1 if adj_lst is int64

__device__ __forceinline__ float tf32_rna(float x) {
    float r;
    asm("cvt.rna.tf32.f32 %0, %1;" : "=f"(r) : "f"(x));
    return r;
}

__device__ __forceinline__ void mma_tf32(float* c, const float* a, const float* b) {
    asm volatile(
        "mma.sync.aligned.m16n8k8.row.col.f32.tf32.tf32.f32 "
        "{%0,%1,%2,%3}, {%4,%5,%6,%7}, {%8,%9}, {%0,%1,%2,%3};\n"
        : "+f"(c[0]), "+f"(c[1]), "+f"(c[2]), "+f"(c[3])
        : "r"(__float_as_uint(a[0])), "r"(__float_as_uint(a[1])),
          "r"(__float_as_uint(a[2])), "r"(__float_as_uint(a[3])),
          "r"(__float_as_uint(b[0])), "r"(__float_as_uint(b[1])));
}

// ---------------- adj dtype detection ----------------
__global__ void detect_adj_kernel(const void* __restrict__ adj) {
    const long long* p = (const long long*)adj;
    int ok = 1;
    for (int i = 0; i < 64; i++) {
        long long v = p[i];
        if (v < 0 || v > (long long)V_N) { ok = 0; break; }
    }
    g_adj64 = ok;
}

// ---------------- wa[h,d] = sum_o W[h,d,o] * a[h,o] ----------------
__global__ void wa_kernel(const float* __restrict__ W, const float* __restrict__ a) {
    int h = blockIdx.x;
    int d = threadIdx.x;            // 256 threads
    const float* Wd = W + ((size_t)h * D_K + d) * O_DIM;
    const float* ah = a + h * O_DIM;
    float s = 0.f;
    #pragma unroll 8
    for (int o = 0; o < O_DIM; o++) s += Wd[o] * ah[o];
    g_wa[h * D_K + d] = s;
}

// ---------------- B repack + tf32 hi/lo split ----------------
__global__ void bprep_kernel(const float* __restrict__ W) {
    int d = blockIdx.x;             // 0..255
    int n = threadIdx.x;            // 0..511
    int h = n >> 7, o = n & 127;
    float w  = W[((size_t)h * D_K + d) * O_DIM + o];
    float hi = tf32_rna(w);
    float lo = tf32_rna(w - hi);
    g_Bh[d * NCOL + n] = hi;
    g_Bl[d * NCOL + n] = lo;
}

// ---------------- attn[h,v] = x[v] . wa[h] ----------------
__global__ __launch_bounds__(128) void attn_kernel(const float* __restrict__ x) {
    int v = blockIdx.x;
    __shared__ float sx[D_K];
    int tid = threadIdx.x;
    const float* xr = x + (size_t)v * D_K;
    sx[tid]       = xr[tid];
    sx[tid + 128] = xr[tid + 128];
    __syncthreads();
    int w = tid >> 5;   // head
    int l = tid & 31;
    const float* wah = g_wa + w * D_K;
    float s = 0.f;
    #pragma unroll
    for (int j = 0; j < 8; j++) {
        int d = l + j * 32;
        s += sx[d] * wah[d];
    }
    #pragma unroll
    for (int off = 16; off; off >>= 1) s += __shfl_xor_sync(0xffffffffu, s, off);
    if (l == 0) g_attn[w * V_N + v] = s;
}

// ---------------- GEMM via tensor cores (3xTF32) ----------------
// g_t[v, n] = sum_d x[v,d] * Bc[d,n],  Bc = repacked W
// Block: 256 thr (8 warps as 4m x 2n), BM=128, BN=128, BK=16.
// Warp tile: 32x64 => 2 m16-tiles x 8 n8-tiles of m16n8k8.
#define GBM 128
#define GBN 128
#define GBK 16
#define SKP 20   // BK + 4 pad (frag loads conflict-free: 20*g+t distinct mod 32)

__global__ __launch_bounds__(256, 1) void gemm_tf32_kernel(const float* __restrict__ x) {
    __shared__ float Ah[GBM][SKP], Al[GBM][SKP];
    __shared__ float Bh[GBN][SKP], Bl[GBN][SKP];

    int tid  = threadIdx.x;
    int wid  = tid >> 5;
    int lane = tid & 31;
    int g = lane >> 2;      // groupID (rows / cols within mma tile)
    int t = lane & 3;       // threadID in group (k / paired cols)
    int wm = (wid & 3) * 32;
    int wn = (wid >> 2) * 64;
    int m0 = blockIdx.x * GBM;
    int n0 = blockIdx.y * GBN;

    float acc[2][8][4];
    #pragma unroll
    for (int i = 0; i < 2; i++)
        #pragma unroll
        for (int j = 0; j < 8; j++)
            #pragma unroll
            for (int q = 0; q < 4; q++) acc[i][j][q] = 0.f;

    for (int kt = 0; kt < D_K; kt += GBK) {
        // ---- A tile: x[m0..m0+127][kt..kt+15], convert to hi/lo ----
        #pragma unroll
        for (int i = 0; i < 2; i++) {
            int f   = tid + i * 256;
            int row = f >> 2;
            int kq  = (f & 3) * 4;
            int gm  = m0 + row;
            float4 v = make_float4(0.f, 0.f, 0.f, 0.f);
            if (gm < V_N) v = *(const float4*)(x + (size_t)gm * D_K + kt + kq);
            float h0 = tf32_rna(v.x), h1 = tf32_rna(v.y), h2 = tf32_rna(v.z), h3 = tf32_rna(v.w);
            Ah[row][kq + 0] = h0;  Al[row][kq + 0] = tf32_rna(v.x - h0);
            Ah[row][kq + 1] = h1;  Al[row][kq + 1] = tf32_rna(v.y - h1);
            Ah[row][kq + 2] = h2;  Al[row][kq + 2] = tf32_rna(v.z - h2);
            Ah[row][kq + 3] = h3;  Al[row][kq + 3] = tf32_rna(v.w - h3);
        }
        // ---- B tile: Bc[kt..kt+15][n0..n0+127] (pre-split hi/lo) ----
        #pragma unroll
        for (int i = 0; i < 2; i++) {
            int f  = tid + i * 256;
            int kr = f >> 5;
            int nq = (f & 31) * 4;
            float4 vh = *(const float4*)(g_Bh + (size_t)(kt + kr) * NCOL + n0 + nq);
            float4 vl = *(const float4*)(g_Bl + (size_t)(kt + kr) * NCOL + n0 + nq);
            Bh[nq + 0][kr] = vh.x;  Bl[nq + 0][kr] = vl.x;
            Bh[nq + 1][kr] = vh.y;  Bl[nq + 1][kr] = vl.y;
            Bh[nq + 2][kr] = vh.z;  Bl[nq + 2][kr] = vl.z;
            Bh[nq + 3][kr] = vh.w;  Bl[nq + 3][kr] = vl.w;
        }
        __syncthreads();

        #pragma unroll
        for (int ks = 0; ks < 2; ks++) {
            int kb = ks * 8;
            float ah[2][4], al[2][4], bh[8][2], bl[8][2];
            #pragma unroll
            for (int mt = 0; mt < 2; mt++) {
                int r = wm + mt * 16 + g;
                ah[mt][0] = Ah[r][kb + t];         al[mt][0] = Al[r][kb + t];
                ah[mt][1] = Ah[r + 8][kb + t];     al[mt][1] = Al[r + 8][kb + t];
                ah[mt][2] = Ah[r][kb + t + 4];     al[mt][2] = Al[r][kb + t + 4];
                ah[mt][3] = Ah[r + 8][kb + t + 4]; al[mt][3] = Al[r + 8][kb + t + 4];
            }
            #pragma unroll
            for (int nt = 0; nt < 8; nt++) {
                int c = wn + nt * 8 + g;
                bh[nt][0] = Bh[c][kb + t];      bl[nt][0] = Bl[c][kb + t];
                bh[nt][1] = Bh[c][kb + t + 4];  bl[nt][1] = Bl[c][kb + t + 4];
            }
            #pragma unroll
            for (int mt = 0; mt < 2; mt++)
                #pragma unroll
                for (int nt = 0; nt < 8; nt++) {
                    mma_tf32(acc[mt][nt], ah[mt], bh[nt]);   // hi*hi
                    mma_tf32(acc[mt][nt], ah[mt], bl[nt]);   // hi*lo
                    mma_tf32(acc[mt][nt], al[mt], bh[nt]);   // lo*hi
                }
        }
        __syncthreads();
    }

    // ---- epilogue ----
    #pragma unroll
    for (int mt = 0; mt < 2; mt++) {
        int row = m0 + wm + mt * 16 + g;
        #pragma unroll
        for (int nt = 0; nt < 8; nt++) {
            int col = n0 + wn + nt * 8 + 2 * t;
            if (row < V_N) {
                float2 v0 = make_float2(acc[mt][nt][0], acc[mt][nt][1]);
                *(float2*)(g_t + (size_t)row * NCOL + col) = v0;
            }
            if (row + 8 < V_N) {
                float2 v1 = make_float2(acc[mt][nt][2], acc[mt][nt][3]);
                *(float2*)(g_t + (size_t)(row + 8) * NCOL + col) = v1;
            }
        }
    }
}

// ---------------- aggregation: softmax over neighbors + weighted sum ----------------
__global__ __launch_bounds__(128) void aggregate_kernel(const void* __restrict__ adj,
                                                        const float* __restrict__ b,
                                                        float* __restrict__ out) {
    int v   = blockIdx.x;
    int tid = threadIdx.x;

    __shared__ float s_score[NHEAD][KNBR];
    __shared__ float s_coef [NHEAD][KNBR];
    __shared__ int   s_idx  [NHEAD][KNBR];

    if (tid < NHEAD * KNBR) {
        int h = tid >> 4;
        int k = tid & 15;
        long long a;
        if (g_adj64) a = ((const long long*)adj)[(size_t)v * KNBR + k];
        else         a = (long long)((const int*)adj)[(size_t)v * KNBR + k];
        bool pad = (a >= (long long)V_N) || (a < 0);
        int n = pad ? -1 : (int)a;
        s_idx[h][k]   = n;
        s_score[h][k] = pad ? -1e9f : g_attn[h * V_N + n];
    }
    __syncthreads();

    if (tid < NHEAD) {
        float mx = -INFINITY;
        #pragma unroll
        for (int k = 0; k < KNBR; k++) mx = fmaxf(mx, s_score[tid][k]);
        float s = 0.f;
        #pragma unroll
        for (int k = 0; k < KNBR; k++) {
            float e = expf(s_score[tid][k] - mx);
            s_score[tid][k] = e;
            s += e;
        }
        float inv = 1.0f / s;
        #pragma unroll
        for (int k = 0; k < KNBR; k++) s_coef[tid][k] = s_score[tid][k] * inv;
    }
    __syncthreads();

    int o = tid;  // 128 threads = O_DIM
    float acc = 0.f;
    #pragma unroll
    for (int h = 0; h < NHEAD; h++) {
        const float* th = g_t + h * O_DIM + o;
        float ah = 0.f;
        #pragma unroll
        for (int k = 0; k < KNBR; k++) {
            int   n = s_idx[h][k];
            float c = s_coef[h][k];
            if (n >= 0) ah = fmaf(c, __ldg(th + (size_t)n * NCOL), ah);
        }
        acc += ah;
    }
    float bm = 0.25f * (b[o] + b[O_DIM + o] + b[2 * O_DIM + o] + b[3 * O_DIM + o]);
    float r  = fmaf(acc, 0.25f, bm);
    out[(size_t)v * O_DIM + o] = fmaxf(r, 0.f);
}

// ---------------- launch ----------------
extern "C" void kernel_launch(void* const* d_in, const int* in_sizes, int n_in,
                              void* d_out, int out_size) {
    const float* x   = (const float*)d_in[0];   // [V, D]
    const float* W   = (const float*)d_in[1];   // [H, D, O]
    const float* a   = (const float*)d_in[2];   // [H, O]
    const float* b   = (const float*)d_in[3];   // [H, O]
    const void*  adj = d_in[4];                 // [V, K] int32 or int64
    float* out = (float*)d_out;                 // [V, O]

    detect_adj_kernel<<<1, 1>>>(adj);
    wa_kernel<<<NHEAD, 256>>>(W, a);
    bprep_kernel<<<D_K, NCOL>>>(W);
    attn_kernel<<<V_N, 128>>>(x);
    dim3 ggrid((V_N + GBM - 1) / GBM, NCOL / GBN);
    gemm_tf32_kernel<<<ggrid, 256>>>(x);
    aggregate_kernel<<<V_N, 128>>>(adj, b, out);
}

// round 4
// speedup vs baseline: 3.3031x; 3.3031x over previous
#include <cuda_runtime.h>
#include <cuda_bf16.h>
#include <math.h>
#include <cstdint>

// Problem constants (fixed by setup_inputs)
#define V_N   20000
#define VPAD  20096          // 157 * 128
#define D_K   256
#define NHEAD 4
#define O_DIM 128
#define NCOL  512            // NHEAD * O_DIM
#define KNBR  16

// ---------------- scratch (no allocations allowed) ----------------
__device__ float    g_t[(size_t)VPAD * NCOL];        // [Vpad, H*O] fp32, 41 MB
__device__ float    g_attn[NHEAD * V_N];
__device__ float    g_wa[NHEAD * D_K];
__device__ uint32_t g_x16h[(size_t)VPAD * (D_K / 2)]; // x bf16 hi, [v][d] packed x2
__device__ uint32_t g_x16l[(size_t)VPAD * (D_K / 2)]; // x bf16 lo residual
__device__ uint32_t g_B16h[NCOL * (D_K / 2)];         // W repacked [n][d] bf16 hi
__device__ uint32_t g_B16l[NCOL * (D_K / 2)];         // lo residual
__device__ int      g_adj64;

// ======================= helpers =======================
__device__ __forceinline__ uint32_t smem_u32(const void* p) {
    uint32_t a;
    asm("{ .reg .u64 t; cvta.to.shared.u64 t, %1; cvt.u32.u64 %0, t; }" : "=r"(a) : "l"(p));
    return a;
}
#define SW128(off) ((off) ^ (((off) >> 3) & 0x70))

#define LDSM4(r, addr) \
    asm volatile("ldmatrix.sync.aligned.m8n8.x4.shared.b16 {%0,%1,%2,%3}, [%4];" \
        : "=r"((r)[0]), "=r"((r)[1]), "=r"((r)[2]), "=r"((r)[3]) : "r"(addr))

#define MMA16(c, a, b) \
    asm volatile("mma.sync.aligned.m16n8k16.row.col.f32.bf16.bf16.f32 " \
        "{%0,%1,%2,%3}, {%4,%5,%6,%7}, {%8,%9}, {%0,%1,%2,%3};" \
        : "+f"((c)[0]), "+f"((c)[1]), "+f"((c)[2]), "+f"((c)[3]) \
        : "r"((a)[0]), "r"((a)[1]), "r"((a)[2]), "r"((a)[3]), "r"((b)[0]), "r"((b)[1]))

#define CP_ASYNC16(dst, src) \
    asm volatile("cp.async.cg.shared.global [%0], [%1], 16;" :: "r"(dst), "l"(src))

__device__ __forceinline__ uint32_t bf16_pack_hi(float a, float b, float& ra, float& rb) {
    __nv_bfloat162 h = __floats2bfloat162_rn(a, b);
    ra = a - __bfloat162float(h.x);
    rb = b - __bfloat162float(h.y);
    return *(uint32_t*)&h;
}
__device__ __forceinline__ uint32_t bf16_pack(float a, float b) {
    __nv_bfloat162 h = __floats2bfloat162_rn(a, b);
    return *(uint32_t*)&h;
}

// ---------------- adj dtype detection ----------------
__global__ void detect_adj_kernel(const void* __restrict__ adj) {
    const long long* p = (const long long*)adj;
    int ok = 1;
    for (int i = 0; i < 64; i++) {
        long long v = p[i];
        if (v < 0 || v > (long long)V_N) { ok = 0; break; }
    }
    g_adj64 = ok;
}

// ---------------- wa[h,d] = sum_o W[h,d,o] * a[h,o] ----------------
__global__ void wa_kernel(const float* __restrict__ W, const float* __restrict__ a) {
    int h = blockIdx.x;
    int d = threadIdx.x;
    const float* Wd = W + ((size_t)h * D_K + d) * O_DIM;
    const float* ah = a + h * O_DIM;
    float s = 0.f;
    #pragma unroll 8
    for (int o = 0; o < O_DIM; o++) s += Wd[o] * ah[o];
    g_wa[h * D_K + d] = s;
}

// ---------------- B repack -> bf16 hi/lo, layout [n][d] ----------------
__global__ void bprep_kernel(const float* __restrict__ W) {
    int n = blockIdx.x;             // 0..511  (h*128+o)
    int t = threadIdx.x;            // 0..127 -> d pair (2t, 2t+1)
    int h = n >> 7, o = n & 127;
    float w0 = W[((size_t)h * D_K + 2 * t)     * O_DIM + o];
    float w1 = W[((size_t)h * D_K + 2 * t + 1) * O_DIM + o];
    float r0, r1;
    uint32_t hi = bf16_pack_hi(w0, w1, r0, r1);
    g_B16h[n * (D_K / 2) + t] = hi;
    g_B16l[n * (D_K / 2) + t] = bf16_pack(r0, r1);
}

// ---------------- x prep: bf16 hi/lo split + fused attn dots ----------------
// One warp per node row. grid = VPAD/8 = 2512, block 256.
__global__ __launch_bounds__(256) void prepx_kernel(const float* __restrict__ x) {
    __shared__ float swa[NHEAD * D_K];
    int tid = threadIdx.x;
    for (int i = tid; i < NHEAD * D_K; i += 256) swa[i] = g_wa[i];
    __syncthreads();

    int wid = tid >> 5, lane = tid & 31;
    int v  = blockIdx.x * 8 + wid;
    int d0 = lane * 8;

    float4 v0 = make_float4(0.f, 0.f, 0.f, 0.f), v1 = v0;
    if (v < V_N) {
        const float* xp = x + (size_t)v * D_K + d0;
        v0 = *(const float4*)xp;
        v1 = *(const float4*)(xp + 4);
    }
    float f[8] = {v0.x, v0.y, v0.z, v0.w, v1.x, v1.y, v1.z, v1.w};
    float r[8];
    uint32_t hw[4], lw[4];
    #pragma unroll
    for (int j = 0; j < 4; j++) {
        hw[j] = bf16_pack_hi(f[2 * j], f[2 * j + 1], r[2 * j], r[2 * j + 1]);
        lw[j] = bf16_pack(r[2 * j], r[2 * j + 1]);
    }
    ((uint4*)g_x16h)[(size_t)v * 32 + lane] = make_uint4(hw[0], hw[1], hw[2], hw[3]);
    ((uint4*)g_x16l)[(size_t)v * 32 + lane] = make_uint4(lw[0], lw[1], lw[2], lw[3]);

    // attn dots (4 heads)
    #pragma unroll
    for (int h = 0; h < NHEAD; h++) {
        const float* wah = swa + h * D_K + d0;
        float s = 0.f;
        #pragma unroll
        for (int j = 0; j < 8; j++) s += f[j] * wah[j];
        #pragma unroll
        for (int off = 16; off; off >>= 1) s += __shfl_xor_sync(0xffffffffu, s, off);
        if (lane == 0 && v < V_N) g_attn[h * V_N + v] = s;
    }
}

// ---------------- GEMM: mma.sync bf16 hi/lo x3, cp.async double buffer ----------------
#define GM 128
#define GN 128
#define KC 64
#define NCHUNK (D_K / KC)   // 4
#define BUFSZ  65536
#define SOA_H  0
#define SOA_L  16384
#define SOB_H  32768
#define SOB_L  49152
#define SMEM_SZ (2 * BUFSZ)  // 131072

__device__ __forceinline__ void load_chunk(uint32_t sb, int buf, int kc,
                                           int m0, int n0, int tid) {
    uint32_t base = sb + buf * BUFSZ;
    #pragma unroll
    for (int i = 0; i < 4; i++) {
        int idx = tid + i * 256;       // 1024 (row,seg) pairs
        int row = idx >> 3, seg = idx & 7;
        uint32_t sw = SW128((uint32_t)(row * 128 + seg * 16));
        size_t   ao = (size_t)(m0 + row) * 32 + kc * 8 + seg;   // uint4 units
        size_t   bo = (size_t)(n0 + row) * 32 + kc * 8 + seg;
        CP_ASYNC16(base + SOA_H + sw, (const uint4*)g_x16h + ao);
        CP_ASYNC16(base + SOA_L + sw, (const uint4*)g_x16l + ao);
        CP_ASYNC16(base + SOB_H + sw, (const uint4*)g_B16h + bo);
        CP_ASYNC16(base + SOB_L + sw, (const uint4*)g_B16l + bo);
    }
    asm volatile("cp.async.commit_group;" ::: "memory");
}

__global__ __launch_bounds__(256) void gemm_mma_kernel() {
    extern __shared__ char smem[];
    uint32_t sb = smem_u32(smem);
    int tid = threadIdx.x, wid = tid >> 5, lane = tid & 31;
    int m0 = blockIdx.x * GM, n0 = blockIdx.y * GN;
    int wm = (wid & 3) * 32, wn = (wid >> 2) * 64;

    float acc[2][8][4];
    #pragma unroll
    for (int i = 0; i < 2; i++)
        #pragma unroll
        for (int j = 0; j < 8; j++)
            #pragma unroll
            for (int q = 0; q < 4; q++) acc[i][j][q] = 0.f;

    int lrA = lane & 15;
    int hA  = lane >> 4;
    int lrB = (lane & 7) + ((lane >> 4) << 3);
    int hB  = (lane >> 3) & 1;

    load_chunk(sb, 0, 0, m0, n0, tid);

    for (int kc = 0; kc < NCHUNK; kc++) {
        if (kc + 1 < NCHUNK) {
            load_chunk(sb, (kc + 1) & 1, kc + 1, m0, n0, tid);
            asm volatile("cp.async.wait_group 1;" ::: "memory");
        } else {
            asm volatile("cp.async.wait_group 0;" ::: "memory");
        }
        __syncthreads();

        uint32_t base = sb + (kc & 1) * BUFSZ;
        #pragma unroll
        for (int ks = 0; ks < 4; ks++) {
            uint32_t a_h[2][4], a_l[2][4];
            #pragma unroll
            for (int mt = 0; mt < 2; mt++) {
                uint32_t off = SW128((uint32_t)((wm + mt * 16 + lrA) * 128 + ks * 32 + hA * 16));
                LDSM4(a_h[mt], base + SOA_H + off);
                LDSM4(a_l[mt], base + SOA_L + off);
            }
            #pragma unroll
            for (int p = 0; p < 4; p++) {
                uint32_t bh[4], bl[4];
                uint32_t off = SW128((uint32_t)((wn + p * 16 + lrB) * 128 + ks * 32 + hB * 16));
                LDSM4(bh, base + SOB_H + off);
                LDSM4(bl, base + SOB_L + off);
                #pragma unroll
                for (int mt = 0; mt < 2; mt++) {
                    MMA16(acc[mt][2 * p],     a_h[mt], &bh[0]);
                    MMA16(acc[mt][2 * p],     a_h[mt], &bl[0]);
                    MMA16(acc[mt][2 * p],     a_l[mt], &bh[0]);
                    MMA16(acc[mt][2 * p + 1], a_h[mt], &bh[2]);
                    MMA16(acc[mt][2 * p + 1], a_h[mt], &bl[2]);
                    MMA16(acc[mt][2 * p + 1], a_l[mt], &bh[2]);
                }
            }
        }
        __syncthreads();
    }

    // epilogue (g_t padded to VPAD rows -> unguarded)
    int g  = lane >> 2;
    int t2 = (lane & 3) * 2;
    #pragma unroll
    for (int mt = 0; mt < 2; mt++) {
        int r0 = m0 + wm + mt * 16 + g;
        #pragma unroll
        for (int nt = 0; nt < 8; nt++) {
            int c = n0 + wn + nt * 8 + t2;
            *(float2*)(g_t + (size_t)r0 * NCOL + c)       = make_float2(acc[mt][nt][0], acc[mt][nt][1]);
            *(float2*)(g_t + (size_t)(r0 + 8) * NCOL + c) = make_float2(acc[mt][nt][2], acc[mt][nt][3]);
        }
    }
}

// ---------------- aggregation: softmax over neighbors + weighted sum ----------------
__global__ __launch_bounds__(128) void aggregate_kernel(const void* __restrict__ adj,
                                                        const float* __restrict__ b,
                                                        float* __restrict__ out) {
    int v   = blockIdx.x;
    int tid = threadIdx.x;

    __shared__ float s_score[NHEAD][KNBR];
    __shared__ float s_coef [NHEAD][KNBR];
    __shared__ int   s_idx  [NHEAD][KNBR];

    if (tid < NHEAD * KNBR) {
        int h = tid >> 4;
        int k = tid & 15;
        long long a;
        if (g_adj64) a = ((const long long*)adj)[(size_t)v * KNBR + k];
        else         a = (long long)((const int*)adj)[(size_t)v * KNBR + k];
        bool pad = (a >= (long long)V_N) || (a < 0);
        int n = pad ? -1 : (int)a;
        s_idx[h][k]   = n;
        s_score[h][k] = pad ? -1e9f : g_attn[h * V_N + n];
    }
    __syncthreads();

    if (tid < NHEAD) {
        float mx = -INFINITY;
        #pragma unroll
        for (int k = 0; k < KNBR; k++) mx = fmaxf(mx, s_score[tid][k]);
        float s = 0.f;
        #pragma unroll
        for (int k = 0; k < KNBR; k++) {
            float e = expf(s_score[tid][k] - mx);
            s_score[tid][k] = e;
            s += e;
        }
        float inv = 1.0f / s;
        #pragma unroll
        for (int k = 0; k < KNBR; k++) s_coef[tid][k] = s_score[tid][k] * inv;
    }
    __syncthreads();

    int o = tid;
    float acc = 0.f;
    #pragma unroll
    for (int h = 0; h < NHEAD; h++) {
        const float* th = g_t + h * O_DIM + o;
        float ah = 0.f;
        #pragma unroll
        for (int k = 0; k < KNBR; k++) {
            int   n = s_idx[h][k];
            float c = s_coef[h][k];
            if (n >= 0) ah = fmaf(c, __ldg(th + (size_t)n * NCOL), ah);
        }
        acc += ah;
    }
    float bm = 0.25f * (b[o] + b[O_DIM + o] + b[2 * O_DIM + o] + b[3 * O_DIM + o]);
    float r  = fmaf(acc, 0.25f, bm);
    out[(size_t)v * O_DIM + o] = fmaxf(r, 0.f);
}

// ---------------- launch ----------------
extern "C" void kernel_launch(void* const* d_in, const int* in_sizes, int n_in,
                              void* d_out, int out_size) {
    const float* x   = (const float*)d_in[0];   // [V, D]
    const float* W   = (const float*)d_in[1];   // [H, D, O]
    const float* a   = (const float*)d_in[2];   // [H, O]
    const float* b   = (const float*)d_in[3];   // [H, O]
    const void*  adj = d_in[4];                 // [V, K] int32 or int64
    float* out = (float*)d_out;                 // [V, O]

    cudaFuncSetAttribute(gemm_mma_kernel, cudaFuncAttributeMaxDynamicSharedMemorySize, SMEM_SZ);

    detect_adj_kernel<<<1, 1>>>(adj);
    wa_kernel<<<NHEAD, 256>>>(W, a);
    bprep_kernel<<<NCOL, 128>>>(W);
    prepx_kernel<<<VPAD / 8, 256>>>(x);
    dim3 ggrid(VPAD / GM, NCOL / GN);
    gemm_mma_kernel<<<ggrid, 256, SMEM_SZ>>>();
    aggregate_kernel<<<V_N, 128>>>(adj, b, out);
}

// round 5
// speedup vs baseline: 4.0166x; 1.2160x over previous
#include <cuda_runtime.h>
#include <cuda_bf16.h>
#include <cuda_fp16.h>
#include <math.h>
#include <cstdint>

// Problem constants (fixed by setup_inputs)
#define V_N   20000
#define VPAD  20096          // 157 * 128
#define D_K   256
#define NHEAD 4
#define O_DIM 128
#define NCOL  512            // NHEAD * O_DIM
#define KNBR  16

// ---------------- scratch (no allocations allowed) ----------------
__device__ __half   g_th[(size_t)VPAD * NCOL];        // t in fp16: [Vpad, H*O], 20.5 MB
__device__ float    g_attn[NHEAD * V_N];
__device__ float    g_wa[NHEAD * D_K];
__device__ uint32_t g_x16h[(size_t)VPAD * (D_K / 2)]; // x bf16 hi, [v][d] packed x2
__device__ uint32_t g_x16l[(size_t)VPAD * (D_K / 2)]; // x bf16 lo residual
__device__ uint32_t g_B16h[NCOL * (D_K / 2)];         // W repacked [n][d] bf16 hi
__device__ uint32_t g_B16l[NCOL * (D_K / 2)];         // lo residual
__device__ int      g_adj64;

// ======================= helpers =======================
__device__ __forceinline__ uint32_t smem_u32(const void* p) {
    uint32_t a;
    asm("{ .reg .u64 t; cvta.to.shared.u64 t, %1; cvt.u32.u64 %0, t; }" : "=r"(a) : "l"(p));
    return a;
}
#define SW128(off) ((off) ^ (((off) >> 3) & 0x70))

#define LDSM4(r, addr) \
    asm volatile("ldmatrix.sync.aligned.m8n8.x4.shared.b16 {%0,%1,%2,%3}, [%4];" \
        : "=r"((r)[0]), "=r"((r)[1]), "=r"((r)[2]), "=r"((r)[3]) : "r"(addr))

#define MMA16(c, a, b) \
    asm volatile("mma.sync.aligned.m16n8k16.row.col.f32.bf16.bf16.f32 " \
        "{%0,%1,%2,%3}, {%4,%5,%6,%7}, {%8,%9}, {%0,%1,%2,%3};" \
        : "+f"((c)[0]), "+f"((c)[1]), "+f"((c)[2]), "+f"((c)[3]) \
        : "r"((a)[0]), "r"((a)[1]), "r"((a)[2]), "r"((a)[3]), "r"((b)[0]), "r"((b)[1]))

#define CP_ASYNC16(dst, src) \
    asm volatile("cp.async.cg.shared.global [%0], [%1], 16;" :: "r"(dst), "l"(src))

__device__ __forceinline__ uint32_t bf16_pack_hi(float a, float b, float& ra, float& rb) {
    __nv_bfloat162 h = __floats2bfloat162_rn(a, b);
    ra = a - __bfloat162float(h.x);
    rb = b - __bfloat162float(h.y);
    return *(uint32_t*)&h;
}
__device__ __forceinline__ uint32_t bf16_pack(float a, float b) {
    __nv_bfloat162 h = __floats2bfloat162_rn(a, b);
    return *(uint32_t*)&h;
}

// ---------------- adj dtype detection ----------------
__global__ void detect_adj_kernel(const void* __restrict__ adj) {
    const long long* p = (const long long*)adj;
    int ok = 1;
    for (int i = 0; i < 64; i++) {
        long long v = p[i];
        if (v < 0 || v > (long long)V_N) { ok = 0; break; }
    }
    g_adj64 = ok;
}

// ---------------- wa[h,d] = sum_o W[h,d,o] * a[h,o] ----------------
__global__ void wa_kernel(const float* __restrict__ W, const float* __restrict__ a) {
    int h = blockIdx.x;
    int d = threadIdx.x;
    const float* Wd = W + ((size_t)h * D_K + d) * O_DIM;
    const float* ah = a + h * O_DIM;
    float s = 0.f;
    #pragma unroll 8
    for (int o = 0; o < O_DIM; o++) s += Wd[o] * ah[o];
    g_wa[h * D_K + d] = s;
}

// ---------------- B repack -> bf16 hi/lo, layout [n][d] ----------------
__global__ void bprep_kernel(const float* __restrict__ W) {
    int n = blockIdx.x;             // 0..511  (h*128+o)
    int t = threadIdx.x;            // 0..127 -> d pair (2t, 2t+1)
    int h = n >> 7, o = n & 127;
    float w0 = W[((size_t)h * D_K + 2 * t)     * O_DIM + o];
    float w1 = W[((size_t)h * D_K + 2 * t + 1) * O_DIM + o];
    float r0, r1;
    uint32_t hi = bf16_pack_hi(w0, w1, r0, r1);
    g_B16h[n * (D_K / 2) + t] = hi;
    g_B16l[n * (D_K / 2) + t] = bf16_pack(r0, r1);
}

// ---------------- x prep: bf16 hi/lo split + fused attn dots ----------------
__global__ __launch_bounds__(256) void prepx_kernel(const float* __restrict__ x) {
    __shared__ float swa[NHEAD * D_K];
    int tid = threadIdx.x;
    for (int i = tid; i < NHEAD * D_K; i += 256) swa[i] = g_wa[i];
    __syncthreads();

    int wid = tid >> 5, lane = tid & 31;
    int v  = blockIdx.x * 8 + wid;
    int d0 = lane * 8;

    float4 v0 = make_float4(0.f, 0.f, 0.f, 0.f), v1 = v0;
    if (v < V_N) {
        const float* xp = x + (size_t)v * D_K + d0;
        v0 = *(const float4*)xp;
        v1 = *(const float4*)(xp + 4);
    }
    float f[8] = {v0.x, v0.y, v0.z, v0.w, v1.x, v1.y, v1.z, v1.w};
    float r[8];
    uint32_t hw[4], lw[4];
    #pragma unroll
    for (int j = 0; j < 4; j++) {
        hw[j] = bf16_pack_hi(f[2 * j], f[2 * j + 1], r[2 * j], r[2 * j + 1]);
        lw[j] = bf16_pack(r[2 * j], r[2 * j + 1]);
    }
    ((uint4*)g_x16h)[(size_t)v * 32 + lane] = make_uint4(hw[0], hw[1], hw[2], hw[3]);
    ((uint4*)g_x16l)[(size_t)v * 32 + lane] = make_uint4(lw[0], lw[1], lw[2], lw[3]);

    #pragma unroll
    for (int h = 0; h < NHEAD; h++) {
        const float* wah = swa + h * D_K + d0;
        float s = 0.f;
        #pragma unroll
        for (int j = 0; j < 8; j++) s += f[j] * wah[j];
        #pragma unroll
        for (int off = 16; off; off >>= 1) s += __shfl_xor_sync(0xffffffffu, s, off);
        if (lane == 0 && v < V_N) g_attn[h * V_N + v] = s;
    }
}

// ---------------- GEMM: mma.sync bf16 hi/lo x3, cp.async double buffer ----------------
#define GM 128
#define GN 128
#define KC 64
#define NCHUNK (D_K / KC)   // 4
#define BUFSZ  65536
#define SOA_H  0
#define SOA_L  16384
#define SOB_H  32768
#define SOB_L  49152
#define SMEM_SZ (2 * BUFSZ)  // 131072

__device__ __forceinline__ void load_chunk(uint32_t sb, int buf, int kc,
                                           int m0, int n0, int tid) {
    uint32_t base = sb + buf * BUFSZ;
    #pragma unroll
    for (int i = 0; i < 4; i++) {
        int idx = tid + i * 256;       // 1024 (row,seg) pairs
        int row = idx >> 3, seg = idx & 7;
        uint32_t sw = SW128((uint32_t)(row * 128 + seg * 16));
        size_t   ao = (size_t)(m0 + row) * 32 + kc * 8 + seg;   // uint4 units
        size_t   bo = (size_t)(n0 + row) * 32 + kc * 8 + seg;
        CP_ASYNC16(base + SOA_H + sw, (const uint4*)g_x16h + ao);
        CP_ASYNC16(base + SOA_L + sw, (const uint4*)g_x16l + ao);
        CP_ASYNC16(base + SOB_H + sw, (const uint4*)g_B16h + bo);
        CP_ASYNC16(base + SOB_L + sw, (const uint4*)g_B16l + bo);
    }
    asm volatile("cp.async.commit_group;" ::: "memory");
}

__global__ __launch_bounds__(256) void gemm_mma_kernel() {
    extern __shared__ char smem[];
    uint32_t sb = smem_u32(smem);
    int tid = threadIdx.x, wid = tid >> 5, lane = tid & 31;
    int m0 = blockIdx.x * GM, n0 = blockIdx.y * GN;
    int wm = (wid & 3) * 32, wn = (wid >> 2) * 64;

    float acc[2][8][4];
    #pragma unroll
    for (int i = 0; i < 2; i++)
        #pragma unroll
        for (int j = 0; j < 8; j++)
            #pragma unroll
            for (int q = 0; q < 4; q++) acc[i][j][q] = 0.f;

    int lrA = lane & 15;
    int hA  = lane >> 4;
    int lrB = (lane & 7) + ((lane >> 4) << 3);
    int hB  = (lane >> 3) & 1;

    load_chunk(sb, 0, 0, m0, n0, tid);

    for (int kc = 0; kc < NCHUNK; kc++) {
        if (kc + 1 < NCHUNK) {
            load_chunk(sb, (kc + 1) & 1, kc + 1, m0, n0, tid);
            asm volatile("cp.async.wait_group 1;" ::: "memory");
        } else {
            asm volatile("cp.async.wait_group 0;" ::: "memory");
        }
        __syncthreads();

        uint32_t base = sb + (kc & 1) * BUFSZ;
        #pragma unroll
        for (int ks = 0; ks < 4; ks++) {
            uint32_t a_h[2][4], a_l[2][4];
            #pragma unroll
            for (int mt = 0; mt < 2; mt++) {
                uint32_t off = SW128((uint32_t)((wm + mt * 16 + lrA) * 128 + ks * 32 + hA * 16));
                LDSM4(a_h[mt], base + SOA_H + off);
                LDSM4(a_l[mt], base + SOA_L + off);
            }
            #pragma unroll
            for (int p = 0; p < 4; p++) {
                uint32_t bh[4], bl[4];
                uint32_t off = SW128((uint32_t)((wn + p * 16 + lrB) * 128 + ks * 32 + hB * 16));
                LDSM4(bh, base + SOB_H + off);
                LDSM4(bl, base + SOB_L + off);
                #pragma unroll
                for (int mt = 0; mt < 2; mt++) {
                    MMA16(acc[mt][2 * p],     a_h[mt], &bh[0]);
                    MMA16(acc[mt][2 * p],     a_h[mt], &bl[0]);
                    MMA16(acc[mt][2 * p],     a_l[mt], &bh[0]);
                    MMA16(acc[mt][2 * p + 1], a_h[mt], &bh[2]);
                    MMA16(acc[mt][2 * p + 1], a_h[mt], &bl[2]);
                    MMA16(acc[mt][2 * p + 1], a_l[mt], &bh[2]);
                }
            }
        }
        __syncthreads();
    }

    // epilogue -> fp16 (g_th padded to VPAD rows -> unguarded)
    int g  = lane >> 2;
    int t2 = (lane & 3) * 2;
    #pragma unroll
    for (int mt = 0; mt < 2; mt++) {
        int r0 = m0 + wm + mt * 16 + g;
        #pragma unroll
        for (int nt = 0; nt < 8; nt++) {
            int c = n0 + wn + nt * 8 + t2;
            __half2 v0 = __float22half2_rn(make_float2(acc[mt][nt][0], acc[mt][nt][1]));
            __half2 v1 = __float22half2_rn(make_float2(acc[mt][nt][2], acc[mt][nt][3]));
            *(__half2*)(g_th + (size_t)r0 * NCOL + c)       = v0;
            *(__half2*)(g_th + (size_t)(r0 + 8) * NCOL + c) = v1;
        }
    }
}

// ---------------- aggregation: 2 nodes/block, 64 thr/node, half2 gathers ----------------
__global__ __launch_bounds__(128) void aggregate_kernel(const void* __restrict__ adj,
                                                        const float* __restrict__ b,
                                                        float* __restrict__ out) {
    int local = threadIdx.x >> 6;      // node within block
    int t     = threadIdx.x & 63;
    int v     = blockIdx.x * 2 + local;

    __shared__ float s_coef[2][NHEAD * KNBR];
    __shared__ int   s_idx [2][NHEAD * KNBR];

    // each of 64 threads owns one (h, k); softmax via 16-lane butterflies
    {
        int k = t & 15;
        long long a;
        if (g_adj64) a = ((const long long*)adj)[(size_t)v * KNBR + k];
        else         a = (long long)((const int*)adj)[(size_t)v * KNBR + k];
        bool pad = (a >= (long long)V_N) || (a < 0);
        int n = pad ? 0 : (int)a;
        int h = t >> 4;
        float sc = pad ? -1e9f : g_attn[h * V_N + n];

        float mx = sc;
        #pragma unroll
        for (int off = 8; off; off >>= 1)
            mx = fmaxf(mx, __shfl_xor_sync(0xffffffffu, mx, off));
        float e = __expf(sc - mx);
        float sum = e;
        #pragma unroll
        for (int off = 8; off; off >>= 1)
            sum += __shfl_xor_sync(0xffffffffu, sum, off);
        s_coef[local][t] = pad ? 0.f : (e / sum);
        s_idx [local][t] = n;
    }
    __syncthreads();

    // gather: thread t handles columns (2t, 2t+1) across all heads
    float2 acc = make_float2(0.f, 0.f);
    const float* cf = s_coef[local];
    const int*   ix = s_idx [local];
    #pragma unroll
    for (int h = 0; h < NHEAD; h++) {
        const __half* th = g_th + h * O_DIM + 2 * t;
        float2 ah = make_float2(0.f, 0.f);
        #pragma unroll
        for (int k = 0; k < KNBR; k++) {
            float c = cf[h * KNBR + k];
            int   n = ix[h * KNBR + k];
            __half2 hv = __ldg((const __half2*)(th + (size_t)n * NCOL));
            float2 fv = __half22float2(hv);
            ah.x = fmaf(c, fv.x, ah.x);
            ah.y = fmaf(c, fv.y, ah.y);
        }
        acc.x += ah.x;
        acc.y += ah.y;
    }
    int o = 2 * t;
    float bmx = 0.25f * (b[o]     + b[O_DIM + o]     + b[2 * O_DIM + o]     + b[3 * O_DIM + o]);
    float bmy = 0.25f * (b[o + 1] + b[O_DIM + o + 1] + b[2 * O_DIM + o + 1] + b[3 * O_DIM + o + 1]);
    float rx = fmaf(acc.x, 0.25f, bmx);
    float ry = fmaf(acc.y, 0.25f, bmy);
    *(float2*)(out + (size_t)v * O_DIM + o) = make_float2(fmaxf(rx, 0.f), fmaxf(ry, 0.f));
}

// ---------------- launch ----------------
extern "C" void kernel_launch(void* const* d_in, const int* in_sizes, int n_in,
                              void* d_out, int out_size) {
    const float* x   = (const float*)d_in[0];   // [V, D]
    const float* W   = (const float*)d_in[1];   // [H, D, O]
    const float* a   = (const float*)d_in[2];   // [H, O]
    const float* b   = (const float*)d_in[3];   // [H, O]
    const void*  adj = d_in[4];                 // [V, K] int32 or int64
    float* out = (float*)d_out;                 // [V, O]

    cudaFuncSetAttribute(gemm_mma_kernel, cudaFuncAttributeMaxDynamicSharedMemorySize, SMEM_SZ);

    detect_adj_kernel<<<1, 1>>>(adj);
    wa_kernel<<<NHEAD, 256>>>(W, a);
    bprep_kernel<<<NCOL, 128>>>(W);
    prepx_kernel<<<VPAD / 8, 256>>>(x);
    dim3 ggrid(VPAD / GM, NCOL / GN);
    gemm_mma_kernel<<<ggrid, 256, SMEM_SZ>>>();
    aggregate_kernel<<<V_N / 2, 128>>>(adj, b, out);
}